// round 1
// baseline (speedup 1.0000x reference)
#include <cuda_runtime.h>
#include <math.h>

// Problem constants (fixed by the dataset).
#define MAX_NODES 50000
#define MAX_EDGES 600000
#define DIM 128          // 32 float4 per row

// ---- scratch (no dynamic allocation allowed) ----
__device__ int   g_counts[MAX_NODES];
__device__ int   g_offs[MAX_NODES + 1];
__device__ int   g_cursor[MAX_NODES];
__device__ int   g_csr_src[MAX_EDGES];   // src node id, CSR (dst-grouped) order
__device__ int   g_epos[MAX_EDGES];      // edge e -> its CSR slot
__device__ float g_logits[MAX_EDGES];    // logits in CSR order

// ---------------------------------------------------------------------------
// K0: zero histogram
__global__ void k_zero(int n) {
    int i = blockIdx.x * blockDim.x + threadIdx.x;
    if (i < n) g_counts[i] = 0;
}

// K1: in-degree histogram
__global__ void k_hist(const int* __restrict__ dst, int E) {
    int i = blockIdx.x * blockDim.x + threadIdx.x;
    if (i < E) atomicAdd(&g_counts[dst[i]], 1);
}

// K2: single-block exclusive scan of counts -> offs (+cursor copy)
__global__ void k_scan(int n) {
    __shared__ int s[1024];
    int carry = 0;
    for (int base = 0; base < n; base += 1024) {
        int i = base + threadIdx.x;
        int v = (i < n) ? g_counts[i] : 0;
        s[threadIdx.x] = v;
        __syncthreads();
        #pragma unroll
        for (int off = 1; off < 1024; off <<= 1) {
            int t = (threadIdx.x >= off) ? s[threadIdx.x - off] : 0;
            __syncthreads();
            s[threadIdx.x] += t;
            __syncthreads();
        }
        int excl = s[threadIdx.x] - v;
        if (i < n) {
            g_offs[i]   = carry + excl;
            g_cursor[i] = carry + excl;
        }
        int tile_sum = s[1023];
        __syncthreads();
        carry += tile_sum;
    }
    if (threadIdx.x == 0) g_offs[n] = carry;
}

// K3: scatter edges into CSR order; remember each edge's slot
__global__ void k_scatter(const int* __restrict__ src, const int* __restrict__ dst, int E) {
    int i = blockIdx.x * blockDim.x + threadIdx.x;
    if (i < E) {
        int pos = atomicAdd(&g_cursor[dst[i]], 1);
        g_csr_src[pos] = src[i];
        g_epos[i]      = pos;
    }
}

// ---------------------------------------------------------------------------
// K4: per-edge logits (warp per edge; lane handles one float4 = 4 dims)
//   prod = h_v[src]*h_v[dst]
//   e    = dot(prod*h_d, W_pi)
//   m    = dot(prod, W_M[:128]) + dot(h_d, W_M[128:])
//   logit = e * sigmoid(m)   -> written at CSR slot
__global__ void k_edge_logits(const float4* __restrict__ hv,
                              const float4* __restrict__ hd,
                              const float4* __restrict__ Wpi,
                              const float4* __restrict__ WM,
                              const int* __restrict__ src,
                              const int* __restrict__ dst,
                              int E) {
    int warp = (blockIdx.x * blockDim.x + threadIdx.x) >> 5;
    int lane = threadIdx.x & 31;
    if (warp >= E) return;
    int e = warp;
    int s = __ldg(&src[e]);
    int d = __ldg(&dst[e]);

    float4 fs = hv[s * 32 + lane];
    float4 fd = hv[d * 32 + lane];
    float4 h  = hd[(size_t)e * 32 + lane];
    float4 wp = __ldg(&Wpi[lane]);
    float4 w1 = __ldg(&WM[lane]);
    float4 w2 = __ldg(&WM[32 + lane]);

    float px = fs.x * fd.x, py = fs.y * fd.y, pz = fs.z * fd.z, pw = fs.w * fd.w;
    float ep = px * h.x * wp.x + py * h.y * wp.y + pz * h.z * wp.z + pw * h.w * wp.w;
    float mp = px * w1.x + py * w1.y + pz * w1.z + pw * w1.w
             + h.x * w2.x + h.y * w2.y + h.z * w2.z + h.w * w2.w;

    #pragma unroll
    for (int o = 16; o; o >>= 1) {
        ep += __shfl_xor_sync(0xFFFFFFFFu, ep, o);
        mp += __shfl_xor_sync(0xFFFFFFFFu, mp, o);
    }
    if (lane == 0) {
        float mask = 1.0f / (1.0f + expf(-mp));
        g_logits[g_epos[e]] = ep * mask;
    }
}

// ---------------------------------------------------------------------------
// K5: warp per destination node: softmax over its in-edges + weighted sum of
//     h_v[src]. No atomics; accumulators live in registers (float4 per lane).
__global__ void k_node_agg(const float4* __restrict__ hv,
                           float4* __restrict__ out,
                           int N) {
    int warp = (blockIdx.x * blockDim.x + threadIdx.x) >> 5;
    int lane = threadIdx.x & 31;
    if (warp >= N) return;
    int beg = g_offs[warp], end = g_offs[warp + 1];

    // pass 1: max
    float mx = -INFINITY;
    for (int j = beg + lane; j < end; j += 32) mx = fmaxf(mx, g_logits[j]);
    #pragma unroll
    for (int o = 16; o; o >>= 1) mx = fmaxf(mx, __shfl_xor_sync(0xFFFFFFFFu, mx, o));

    // pass 2: sum of exp
    float se = 0.0f;
    for (int j = beg + lane; j < end; j += 32) se += expf(g_logits[j] - mx);
    #pragma unroll
    for (int o = 16; o; o >>= 1) se += __shfl_xor_sync(0xFFFFFFFFu, se, o);
    float inv = (se > 0.0f) ? 1.0f / se : 0.0f;

    // pass 3: weighted feature aggregation (broadcast scalar, coalesced float4)
    float4 acc = make_float4(0.f, 0.f, 0.f, 0.f);
    for (int j = beg; j < end; j++) {
        float a = expf(g_logits[j] - mx) * inv;
        int s = g_csr_src[j];
        float4 v = hv[s * 32 + lane];
        acc.x += a * v.x; acc.y += a * v.y; acc.z += a * v.z; acc.w += a * v.w;
    }
    out[warp * 32 + lane] = acc;
}

// ---------------------------------------------------------------------------
extern "C" void kernel_launch(void* const* d_in, const int* in_sizes, int n_in,
                              void* d_out, int out_size) {
    const float4* hv  = (const float4*)d_in[0];   // h_v  [N,128]
    const float4* hd  = (const float4*)d_in[1];   // h_d  [E,128]
    const float4* Wpi = (const float4*)d_in[2];   // W_pi [128,1]
    const float4* WM  = (const float4*)d_in[3];   // W_M  [256,1]
    const int*    src = (const int*)d_in[4];      // [E] int32
    const int*    dst = (const int*)d_in[5];      // [E] int32

    int N = in_sizes[0] / DIM;
    int E = in_sizes[4];

    // CSR build
    k_zero   <<<(N + 255) / 256, 256>>>(N);
    k_hist   <<<(E + 255) / 256, 256>>>(dst, E);
    k_scan   <<<1, 1024>>>(N);
    k_scatter<<<(E + 255) / 256, 256>>>(src, dst, E);

    // per-edge logits: warp per edge, 8 warps/block
    {
        int blocks = (E + 7) / 8;
        k_edge_logits<<<blocks, 256>>>(hv, hd, Wpi, WM, src, dst, E);
    }

    // per-node softmax + aggregation: warp per node
    {
        int blocks = (N + 7) / 8;
        k_node_agg<<<blocks, 256>>>(hv, (float4*)d_out, N);
    }
}

// round 3
// speedup vs baseline: 1.4630x; 1.4630x over previous
#include <cuda_runtime.h>
#include <math.h>

#define MAX_NODES 50000
#define MAX_EDGES 600000
#define DIM 128              // 32 float4 per row
#define SCAN_TILE 1024
#define MAX_TILES ((MAX_NODES + SCAN_TILE - 1) / SCAN_TILE)   // 49

// ---- scratch (no dynamic allocation allowed) ----
__device__ int   g_counts[MAX_NODES];
__device__ int   g_offs[MAX_NODES + 1];
__device__ int   g_cursor[MAX_NODES];
__device__ int   g_bsum[MAX_TILES];
__device__ int   g_csr_src[MAX_EDGES];   // src node id, CSR (dst-grouped) order
__device__ int   g_epos[MAX_EDGES];      // edge e -> its CSR slot
__device__ float g_logits[MAX_EDGES];    // logits (later: exp values) in CSR order

// ---------------------------------------------------------------------------
__global__ void k_zero(int n4) {           // n4 = ceil(n/4), int4 stores
    int i = blockIdx.x * blockDim.x + threadIdx.x;
    if (i < n4) ((int4*)g_counts)[i] = make_int4(0, 0, 0, 0);
}

__global__ void k_hist(const int* __restrict__ dst, int E) {
    int i = blockIdx.x * blockDim.x + threadIdx.x;
    if (i < E) atomicAdd(&g_counts[dst[i]], 1);
}

// Scan stage 1: per-tile exclusive scan (49 blocks in parallel) + tile sums
__global__ void k_scan_part(int n) {
    __shared__ int s[SCAN_TILE];
    int i = blockIdx.x * SCAN_TILE + threadIdx.x;
    int v = (i < n) ? g_counts[i] : 0;
    s[threadIdx.x] = v;
    __syncthreads();
    #pragma unroll
    for (int off = 1; off < SCAN_TILE; off <<= 1) {
        int t = (threadIdx.x >= off) ? s[threadIdx.x - off] : 0;
        __syncthreads();
        s[threadIdx.x] += t;
        __syncthreads();
    }
    if (i < n) g_offs[i] = s[threadIdx.x] - v;       // tile-local exclusive
    if (threadIdx.x == SCAN_TILE - 1) g_bsum[blockIdx.x] = s[SCAN_TILE - 1];
}

// Scan stage 2: exclusive scan of the (<=49) tile sums, single tiny block
__global__ void k_scan_bsum(int nb) {
    __shared__ int s[64];
    int v = (threadIdx.x < nb) ? g_bsum[threadIdx.x] : 0;
    s[threadIdx.x] = v;
    __syncthreads();
    #pragma unroll
    for (int off = 1; off < 64; off <<= 1) {
        int t = (threadIdx.x >= off) ? s[threadIdx.x - off] : 0;
        __syncthreads();
        s[threadIdx.x] += t;
        __syncthreads();
    }
    if (threadIdx.x < nb) g_bsum[threadIdx.x] = s[threadIdx.x] - v;
}

// Scan stage 3: add tile offsets, mirror into cursor, close offs[n]
__global__ void k_scan_add(int n, int E) {
    int i = blockIdx.x * SCAN_TILE + threadIdx.x;
    if (i < n) {
        int off = g_offs[i] + g_bsum[blockIdx.x];
        g_offs[i]   = off;
        g_cursor[i] = off;
    }
    if (blockIdx.x == 0 && threadIdx.x == 0) g_offs[n] = E;
}

__global__ void k_scatter(const int* __restrict__ src, const int* __restrict__ dst, int E) {
    int i = blockIdx.x * blockDim.x + threadIdx.x;
    if (i < E) {
        int pos = atomicAdd(&g_cursor[dst[i]], 1);
        g_csr_src[pos] = src[i];
        g_epos[i]      = pos;
    }
}

// ---------------------------------------------------------------------------
// K4: per-edge logits (warp per edge; lane handles one float4 = 4 dims)
//   prod = h_v[src]*h_v[dst]
//   e    = dot(prod*h_d, W_pi)
//   m    = dot(prod, W_M[:128]) + dot(h_d, W_M[128:])
//   logit = e * sigmoid(m)   -> written at CSR slot
__global__ void __launch_bounds__(256)
k_edge_logits(const float4* __restrict__ hv,
              const float4* __restrict__ hd,
              const float4* __restrict__ Wpi,
              const float4* __restrict__ WM,
              const int* __restrict__ src,
              const int* __restrict__ dst,
              int E) {
    int warp = (blockIdx.x * blockDim.x + threadIdx.x) >> 5;
    int lane = threadIdx.x & 31;
    if (warp >= E) return;
    int e = warp;
    int s = __ldg(&src[e]);
    int d = __ldg(&dst[e]);

    float4 fs = hv[s * 32 + lane];
    float4 fd = hv[d * 32 + lane];
    float4 h  = __ldcs(&hd[(size_t)e * 32 + lane]);   // streamed once: evict-first
    float4 wp = __ldg(&Wpi[lane]);
    float4 w1 = __ldg(&WM[lane]);
    float4 w2 = __ldg(&WM[32 + lane]);

    float px = fs.x * fd.x, py = fs.y * fd.y, pz = fs.z * fd.z, pw = fs.w * fd.w;
    float ep = px * h.x * wp.x + py * h.y * wp.y + pz * h.z * wp.z + pw * h.w * wp.w;
    float mp = px * w1.x + py * w1.y + pz * w1.z + pw * w1.w
             + h.x * w2.x + h.y * w2.y + h.z * w2.z + h.w * w2.w;

    #pragma unroll
    for (int o = 16; o; o >>= 1) {
        ep += __shfl_xor_sync(0xFFFFFFFFu, ep, o);
        mp += __shfl_xor_sync(0xFFFFFFFFu, mp, o);
    }
    if (lane == 0) {
        float mask = 1.0f / (1.0f + expf(-mp));
        g_logits[g_epos[e]] = ep * mask;
    }
}

// ---------------------------------------------------------------------------
// K5: warp per destination node: softmax over its in-edges + weighted sum of
//     h_v[src]. Pass 2 caches exp(logit-max) back into g_logits.
__global__ void __launch_bounds__(256)
k_node_agg(const float4* __restrict__ hv,
           float4* __restrict__ out,
           int N) {
    int warp = (blockIdx.x * blockDim.x + threadIdx.x) >> 5;
    int lane = threadIdx.x & 31;
    if (warp >= N) return;
    int beg = g_offs[warp], end = g_offs[warp + 1];

    // pass 1: max
    float mx = -INFINITY;
    for (int j = beg + lane; j < end; j += 32) mx = fmaxf(mx, g_logits[j]);
    #pragma unroll
    for (int o = 16; o; o >>= 1) mx = fmaxf(mx, __shfl_xor_sync(0xFFFFFFFFu, mx, o));

    // pass 2: exp + sum; overwrite logits with exp values (warp-private range)
    float se = 0.0f;
    for (int j = beg + lane; j < end; j += 32) {
        float ex = expf(g_logits[j] - mx);
        g_logits[j] = ex;
        se += ex;
    }
    #pragma unroll
    for (int o = 16; o; o >>= 1) se += __shfl_xor_sync(0xFFFFFFFFu, se, o);
    float inv = (se > 0.0f) ? 1.0f / se : 0.0f;
    __syncwarp();

    // pass 3: weighted feature aggregation (broadcast scalar, coalesced float4)
    float4 acc = make_float4(0.f, 0.f, 0.f, 0.f);
    for (int j = beg; j < end; j++) {
        float a = g_logits[j] * inv;
        int s = g_csr_src[j];
        float4 v = hv[s * 32 + lane];
        acc.x += a * v.x; acc.y += a * v.y; acc.z += a * v.z; acc.w += a * v.w;
    }
    out[warp * 32 + lane] = acc;
}

// ---------------------------------------------------------------------------
extern "C" void kernel_launch(void* const* d_in, const int* in_sizes, int n_in,
                              void* d_out, int out_size) {
    const float4* hv  = (const float4*)d_in[0];
    const float4* hd  = (const float4*)d_in[1];
    const float4* Wpi = (const float4*)d_in[2];
    const float4* WM  = (const float4*)d_in[3];
    const int*    src = (const int*)d_in[4];
    const int*    dst = (const int*)d_in[5];

    int N = in_sizes[0] / DIM;
    int E = in_sizes[4];
    int tiles = (N + SCAN_TILE - 1) / SCAN_TILE;
    int n4 = (N + 3) / 4;

    // CSR build (fully parallel scan)
    k_zero     <<<(n4 + 255) / 256, 256>>>(n4);
    k_hist     <<<(E + 255) / 256, 256>>>(dst, E);
    k_scan_part<<<tiles, SCAN_TILE>>>(N);
    k_scan_bsum<<<1, 64>>>(tiles);
    k_scan_add <<<tiles, SCAN_TILE>>>(N, E);
    k_scatter  <<<(E + 255) / 256, 256>>>(src, dst, E);

    // per-edge logits: warp per edge, 8 warps/block
    k_edge_logits<<<(E + 7) / 8, 256>>>(hv, hd, Wpi, WM, src, dst, E);

    // per-node softmax + aggregation: warp per node
    k_node_agg<<<(N + 7) / 8, 256>>>(hv, (float4*)d_out, N);
}

// round 4
// speedup vs baseline: 1.4680x; 1.0034x over previous
#include <cuda_runtime.h>
#include <math.h>

#define MAX_NODES 50000
#define MAX_EDGES 600000
#define DIM 128              // 32 float4 per row
#define SCAN_TILE 1024
#define MAX_TILES ((MAX_NODES + SCAN_TILE - 1) / SCAN_TILE)   // 49

// ---- scratch (no dynamic allocation; __device__ globals are zero-init) ----
__device__ int   g_counts[MAX_NODES];      // invariant: zero at call entry
__device__ int   g_offs[MAX_NODES + 1];
__device__ int   g_cursor[MAX_NODES];
__device__ int   g_bsum[MAX_TILES];
__device__ int   g_csr_src[MAX_EDGES];     // src node id, CSR (dst-grouped) order
__device__ int   g_csr_eid[MAX_EDGES];     // original edge id per CSR slot
__device__ int   g_csr_dst[MAX_EDGES];     // dst node id per CSR slot
__device__ float g_logits[MAX_EDGES];      // logits (later: exp values), CSR order

// ---------------------------------------------------------------------------
__global__ void k_hist(const int* __restrict__ dst, int E) {
    int i = blockIdx.x * blockDim.x + threadIdx.x;
    if (i < E) atomicAdd(&g_counts[dst[i]], 1);
}

// Scan stage 1: per-tile exclusive scan (49 blocks in parallel) + tile sums
__global__ void k_scan_part(int n) {
    __shared__ int s[SCAN_TILE];
    int i = blockIdx.x * SCAN_TILE + threadIdx.x;
    int v = (i < n) ? g_counts[i] : 0;
    s[threadIdx.x] = v;
    __syncthreads();
    #pragma unroll
    for (int off = 1; off < SCAN_TILE; off <<= 1) {
        int t = (threadIdx.x >= off) ? s[threadIdx.x - off] : 0;
        __syncthreads();
        s[threadIdx.x] += t;
        __syncthreads();
    }
    if (i < n) g_offs[i] = s[threadIdx.x] - v;       // tile-local exclusive
    if (threadIdx.x == SCAN_TILE - 1) g_bsum[blockIdx.x] = s[SCAN_TILE - 1];
}

// Scan stage 2+3 fused: every block redundantly prefix-sums the <=49 tile
// sums from smem (cheap), adds its tile offset, mirrors into cursor, zeroes
// g_counts for the next call (self-restoring scratch), closes offs[n].
__global__ void k_scan_add(int n, int E, int tiles) {
    __shared__ int sb[MAX_TILES];
    if (threadIdx.x < tiles) sb[threadIdx.x] = g_bsum[threadIdx.x];
    __syncthreads();
    int base = 0;
    for (int k = 0; k < blockIdx.x; k++) base += sb[k];   // <=48 smem-broadcast adds

    int i = blockIdx.x * SCAN_TILE + threadIdx.x;
    if (i < n) {
        int off = g_offs[i] + base;
        g_offs[i]   = off;
        g_cursor[i] = off;
        g_counts[i] = 0;                  // restore invariant for next call
    }
    if (blockIdx.x == 0 && threadIdx.x == 0) g_offs[n] = E;
}

// Scatter edges into CSR order, recording (src, edge_id, dst) per slot.
__global__ void k_scatter(const int* __restrict__ src, const int* __restrict__ dst, int E) {
    int i = blockIdx.x * blockDim.x + threadIdx.x;
    if (i < E) {
        int d = dst[i];
        int pos = atomicAdd(&g_cursor[d], 1);
        g_csr_src[pos] = src[i];
        g_csr_eid[pos] = i;
        g_csr_dst[pos] = d;
    }
}

// ---------------------------------------------------------------------------
// K4: per-CSR-slot logits (warp per slot; lane handles one float4 = 4 dims).
// Iterating in CSR order makes consecutive warps share the same h_v[dst] row,
// turning the fd gather stream into L1 hits. Logit store is sequential.
__global__ void __launch_bounds__(512)
k_edge_logits(const float4* __restrict__ hv,
              const float4* __restrict__ hd,
              const float4* __restrict__ Wpi,
              const float4* __restrict__ WM,
              int E) {
    int slot = (blockIdx.x * blockDim.x + threadIdx.x) >> 5;
    int lane = threadIdx.x & 31;
    if (slot >= E) return;
    int s  = __ldg(&g_csr_src[slot]);
    int e  = __ldg(&g_csr_eid[slot]);
    int dn = __ldg(&g_csr_dst[slot]);

    float4 fs = hv[s * 32 + lane];
    float4 fd = hv[dn * 32 + lane];                   // shared across ~12 consecutive slots
    float4 h  = __ldcs(&hd[(size_t)e * 32 + lane]);   // streamed once: evict-first
    float4 wp = __ldg(&Wpi[lane]);
    float4 w1 = __ldg(&WM[lane]);
    float4 w2 = __ldg(&WM[32 + lane]);

    float px = fs.x * fd.x, py = fs.y * fd.y, pz = fs.z * fd.z, pw = fs.w * fd.w;
    float ep = px * h.x * wp.x + py * h.y * wp.y + pz * h.z * wp.z + pw * h.w * wp.w;
    float mp = px * w1.x + py * w1.y + pz * w1.z + pw * w1.w
             + h.x * w2.x + h.y * w2.y + h.z * w2.z + h.w * w2.w;

    #pragma unroll
    for (int o = 16; o; o >>= 1) {
        ep += __shfl_xor_sync(0xFFFFFFFFu, ep, o);
        mp += __shfl_xor_sync(0xFFFFFFFFu, mp, o);
    }
    if (lane == 0) {
        float mask = 1.0f / (1.0f + expf(-mp));
        g_logits[slot] = ep * mask;                   // sequential store
    }
}

// ---------------------------------------------------------------------------
// K5: warp per destination node: softmax over its in-edges + weighted sum of
//     h_v[src]. Pass 2 caches exp(logit-max) back into g_logits.
__global__ void __launch_bounds__(256)
k_node_agg(const float4* __restrict__ hv,
           float4* __restrict__ out,
           int N) {
    int warp = (blockIdx.x * blockDim.x + threadIdx.x) >> 5;
    int lane = threadIdx.x & 31;
    if (warp >= N) return;
    int beg = g_offs[warp], end = g_offs[warp + 1];

    // pass 1: max
    float mx = -INFINITY;
    for (int j = beg + lane; j < end; j += 32) mx = fmaxf(mx, g_logits[j]);
    #pragma unroll
    for (int o = 16; o; o >>= 1) mx = fmaxf(mx, __shfl_xor_sync(0xFFFFFFFFu, mx, o));

    // pass 2: exp + sum; overwrite logits with exp values (warp-private range)
    float se = 0.0f;
    for (int j = beg + lane; j < end; j += 32) {
        float ex = expf(g_logits[j] - mx);
        g_logits[j] = ex;
        se += ex;
    }
    #pragma unroll
    for (int o = 16; o; o >>= 1) se += __shfl_xor_sync(0xFFFFFFFFu, se, o);
    float inv = (se > 0.0f) ? 1.0f / se : 0.0f;
    __syncwarp();

    // pass 3: weighted feature aggregation, 2x unrolled for load MLP
    float4 acc = make_float4(0.f, 0.f, 0.f, 0.f);
    int j = beg;
    for (; j + 1 < end; j += 2) {
        float a0 = g_logits[j]     * inv;
        float a1 = g_logits[j + 1] * inv;
        int s0 = g_csr_src[j];
        int s1 = g_csr_src[j + 1];
        float4 v0 = hv[s0 * 32 + lane];
        float4 v1 = hv[s1 * 32 + lane];
        acc.x += a0 * v0.x + a1 * v1.x;
        acc.y += a0 * v0.y + a1 * v1.y;
        acc.z += a0 * v0.z + a1 * v1.z;
        acc.w += a0 * v0.w + a1 * v1.w;
    }
    if (j < end) {
        float a = g_logits[j] * inv;
        int s = g_csr_src[j];
        float4 v = hv[s * 32 + lane];
        acc.x += a * v.x; acc.y += a * v.y; acc.z += a * v.z; acc.w += a * v.w;
    }
    out[warp * 32 + lane] = acc;
}

// ---------------------------------------------------------------------------
extern "C" void kernel_launch(void* const* d_in, const int* in_sizes, int n_in,
                              void* d_out, int out_size) {
    const float4* hv  = (const float4*)d_in[0];
    const float4* hd  = (const float4*)d_in[1];
    const float4* Wpi = (const float4*)d_in[2];
    const float4* WM  = (const float4*)d_in[3];
    const int*    src = (const int*)d_in[4];
    const int*    dst = (const int*)d_in[5];

    int N = in_sizes[0] / DIM;
    int E = in_sizes[4];
    int tiles = (N + SCAN_TILE - 1) / SCAN_TILE;

    // CSR build (counts are zero at entry; k_scan_add re-zeroes them)
    k_hist     <<<(E + 255) / 256, 256>>>(dst, E);
    k_scan_part<<<tiles, SCAN_TILE>>>(N);
    k_scan_add <<<tiles, SCAN_TILE>>>(N, E, tiles);
    k_scatter  <<<(E + 255) / 256, 256>>>(src, dst, E);

    // per-slot logits in CSR order: warp per slot, 16 warps/block
    k_edge_logits<<<(E + 15) / 16, 512>>>(hv, hd, Wpi, WM, E);

    // per-node softmax + aggregation: warp per node
    k_node_agg<<<(N + 7) / 8, 256>>>(hv, (float4*)d_out, N);
}